// round 9
// baseline (speedup 1.0000x reference)
#include <cuda_runtime.h>
#include <cuda_fp16.h>
#include <math.h>
#include <stdint.h>

#define NU 50000
#define NI 30000
#define NN 80000
#define DD 64

#define NNZ_UI 1000000
#define NNZ_R  800000
#define NNZ_II 300000

// ---------------- scratch (static device globals) -----------------------------
__device__ float  g_cat1[NN * DD];
__device__ float  g_cat2[NN * DD];
__device__ float  g_img_ui[NN * DD];
__device__ float  g_txt_ui[NN * DD];
__device__ float  g_gi1[NI * DD];
__device__ float  g_gt1[NI * DD];
__device__ __half g_cat0h[NN * DD];
__device__ __half g_cat1h[NN * DD];
__device__ __half g_gi0h[NI * DD];
__device__ __half g_gi1h[NI * DD];
__device__ __half g_gt0h[NI * DD];
__device__ __half g_gt1h[NI * DD];
__device__ __half g_iih[NI * DD];
__device__ __half g_ith[NI * DD];

__device__ __forceinline__ float lrelu(float x) { return x >= 0.f ? x : 0.01f * x; }

__device__ __forceinline__ void red4(float* dst, float v, float4 x) {
    asm volatile("red.global.add.v4.f32 [%0], {%1, %2, %3, %4};"
                 :: "l"(dst), "f"(v * x.x), "f"(v * x.y), "f"(v * x.z), "f"(v * x.w)
                 : "memory");
}

__device__ __forceinline__ uint32_t f2tf32(float f) {
    uint32_t r;
    asm("cvt.rna.tf32.f32 %0, %1;" : "=r"(r) : "f"(f));
    return r;
}

__device__ __forceinline__ void mma_tf32(float& c0, float& c1, float& c2, float& c3,
                                         uint32_t a0, uint32_t a1, uint32_t a2, uint32_t a3,
                                         uint32_t b0, uint32_t b1) {
    asm("mma.sync.aligned.m16n8k8.row.col.f32.tf32.tf32.f32 "
        "{%0,%1,%2,%3}, {%4,%5,%6,%7}, {%8,%9}, {%0,%1,%2,%3};"
        : "+f"(c0), "+f"(c1), "+f"(c2), "+f"(c3)
        : "r"(a0), "r"(a1), "r"(a2), "r"(a3), "r"(b0), "r"(b1));
}

// ---------------- fp32 -> fp16 convert -----------------------------------------
__global__ void f2h_kernel(const float* __restrict__ src, __half* __restrict__ dst, int n4) {
    int i = blockIdx.x * blockDim.x + threadIdx.x;
    if (i >= n4) return;
    float4 v = __ldg(reinterpret_cast<const float4*>(src) + i);
    __half2 a = __floats2half2_rn(v.x, v.y);
    __half2 b = __floats2half2_rn(v.z, v.w);
    reinterpret_cast<__half2*>(dst)[i * 2]     = a;
    reinterpret_cast<__half2*>(dst)[i * 2 + 1] = b;
}

// ---------------- spmm with fp16 gather, fp32 RED ------------------------------
// 8 threads/edge; thread j loads 8 halfs (16B), REDs 8 floats.
__global__ void spmm_h_kernel(const int* __restrict__ rows, const int* __restrict__ cols,
                              const float* __restrict__ vals, const __half* __restrict__ xh,
                              float* __restrict__ out, int nnz) {
    int t = blockIdx.x * blockDim.x + threadIdx.x;
    int e = t >> 3;
    if (e >= nnz) return;
    int j = t & 7;

    int   c = __ldg(&cols[e]);
    int   r = __ldg(&rows[e]);
    float v = __ldg(&vals[e]);
    uint4 raw = __ldg(reinterpret_cast<const uint4*>(xh + (size_t)c * 64) + j);
    const __half2* h2 = reinterpret_cast<const __half2*>(&raw);
    float2 f0 = __half22float2(h2[0]);
    float2 f1 = __half22float2(h2[1]);
    float2 f2 = __half22float2(h2[2]);
    float2 f3 = __half22float2(h2[3]);
    float* dst = out + (size_t)r * 64 + j * 8;
    red4(dst,     v, make_float4(f0.x, f0.y, f1.x, f1.y));
    red4(dst + 4, v, make_float4(f2.x, f2.y, f3.x, f3.y));
}

// ---------------- dual spmm over R (fp16 gathers, fp32 REDs) -------------------
__global__ void spmm_dualR_h_kernel(const int* __restrict__ rows, const int* __restrict__ cols,
                                    const float* __restrict__ vals,
                                    const __half* __restrict__ xi, const __half* __restrict__ xt,
                                    float* __restrict__ oi, float* __restrict__ ot, int nnz) {
    int t = blockIdx.x * blockDim.x + threadIdx.x;
    int e = t >> 3;
    if (e >= nnz) return;
    int j = t & 7;

    int   c = __ldg(&cols[e]);
    int   r = __ldg(&rows[e]);
    float v = __ldg(&vals[e]);
    uint4 ra = __ldg(reinterpret_cast<const uint4*>(xi + (size_t)c * 64) + j);
    uint4 rb = __ldg(reinterpret_cast<const uint4*>(xt + (size_t)c * 64) + j);
    const __half2* ha = reinterpret_cast<const __half2*>(&ra);
    const __half2* hb = reinterpret_cast<const __half2*>(&rb);
    float2 a0 = __half22float2(ha[0]), a1 = __half22float2(ha[1]);
    float2 a2 = __half22float2(ha[2]), a3 = __half22float2(ha[3]);
    float2 b0 = __half22float2(hb[0]), b1 = __half22float2(hb[1]);
    float2 b2 = __half22float2(hb[2]), b3 = __half22float2(hb[3]);
    float* di = oi + (size_t)r * 64 + j * 8;
    float* dt = ot + (size_t)r * 64 + j * 8;
    red4(di,     v, make_float4(a0.x, a0.y, a1.x, a1.y));
    red4(di + 4, v, make_float4(a2.x, a2.y, a3.x, a3.y));
    red4(dt,     v, make_float4(b0.x, b0.y, b1.x, b1.y));
    red4(dt + 4, v, make_float4(b2.x, b2.y, b3.x, b3.y));
}

// ---------------- mean3 -> out[0] ----------------------------------------------
__global__ void mean3_cat_kernel(const float* __restrict__ item_emb,
                                 const float* __restrict__ user_emb,
                                 const float* __restrict__ b, const float* __restrict__ c,
                                 float* __restrict__ out) {
    int i = blockIdx.x * blockDim.x + threadIdx.x;
    const int NI4 = NI * 16, NN4 = NN * 16;
    if (i >= NN4) return;
    float4 A = (i < NI4) ? __ldg(reinterpret_cast<const float4*>(item_emb) + i)
                         : __ldg(reinterpret_cast<const float4*>(user_emb) + (i - NI4));
    float4 B = reinterpret_cast<const float4*>(b)[i];
    float4 C = reinterpret_cast<const float4*>(c)[i];
    const float s = 1.f / 3.f;
    reinterpret_cast<float4*>(out)[i] =
        make_float4((A.x + B.x + C.x) * s, (A.y + B.y + C.y) * s,
                    (A.z + B.z + C.z) * s, (A.w + B.w + C.w) * s);
}

// ---------------- tf32 tensor-core projection + BN + lrelu + gate --------------
// Output: fp16 gated item embeddings (feeds fp16-gather spmm).
#define XPITCH 68
template <int F>
__global__ __launch_bounds__(256)
void projgate_kernel(const float* __restrict__ x, const float* __restrict__ W,
                     const float* __restrict__ b, const float* __restrict__ g,
                     const float* __restrict__ beta,
                     const float* __restrict__ Wg, const float* __restrict__ bg,
                     const float* __restrict__ item_emb,
                     __half* __restrict__ outh) {
    __shared__ uint32_t sX[128 * XPITCH];
    __shared__ uint32_t sWt[64 * XPITCH];

    const int tid  = threadIdx.x;
    const int warp = tid >> 5;
    const int lane = tid & 31;
    const int gq   = lane >> 2;
    const int tg   = lane & 3;
    const int wr   = warp * 16;
    const int r0   = blockIdx.x * 128;

    float acc[8][4];
#pragma unroll
    for (int nb = 0; nb < 8; nb++)
#pragma unroll
        for (int i = 0; i < 4; i++) acc[nb][i] = 0.f;

    for (int kc = 0; kc < F; kc += 64) {
        {
            int lr = tid >> 1, half = tid & 1;
            int gr = r0 + lr;
            uint32_t* dst = &sX[lr * XPITCH + half * 32];
            if (gr < NI) {
                const float4* src = reinterpret_cast<const float4*>(x + (size_t)gr * F + kc) + half * 8;
#pragma unroll
                for (int i = 0; i < 8; i++) {
                    float4 v = __ldg(src + i);
                    dst[i * 4 + 0] = f2tf32(v.x);
                    dst[i * 4 + 1] = f2tf32(v.y);
                    dst[i * 4 + 2] = f2tf32(v.z);
                    dst[i * 4 + 3] = f2tf32(v.w);
                }
            } else {
#pragma unroll
                for (int i = 0; i < 32; i++) dst[i] = 0u;
            }
        }
        {
            int wk = tid >> 2, ng = (tid & 3) * 16;
            const float4* src = reinterpret_cast<const float4*>(&W[(size_t)(kc + wk) * 64 + ng]);
#pragma unroll
            for (int i = 0; i < 4; i++) {
                float4 v = __ldg(src + i);
                int n = ng + i * 4;
                sWt[(n + 0) * XPITCH + wk] = f2tf32(v.x);
                sWt[(n + 1) * XPITCH + wk] = f2tf32(v.y);
                sWt[(n + 2) * XPITCH + wk] = f2tf32(v.z);
                sWt[(n + 3) * XPITCH + wk] = f2tf32(v.w);
            }
        }
        __syncthreads();

#pragma unroll
        for (int ks = 0; ks < 8; ks++) {
            int k4 = ks * 8;
            uint32_t a0 = sX[(wr + gq) * XPITCH + k4 + tg];
            uint32_t a1 = sX[(wr + gq + 8) * XPITCH + k4 + tg];
            uint32_t a2 = sX[(wr + gq) * XPITCH + k4 + tg + 4];
            uint32_t a3 = sX[(wr + gq + 8) * XPITCH + k4 + tg + 4];
#pragma unroll
            for (int nb = 0; nb < 8; nb++) {
                uint32_t b0 = sWt[(nb * 8 + gq) * XPITCH + k4 + tg];
                uint32_t b1 = sWt[(nb * 8 + gq) * XPITCH + k4 + tg + 4];
                mma_tf32(acc[nb][0], acc[nb][1], acc[nb][2], acc[nb][3],
                         a0, a1, a2, a3, b0, b1);
            }
        }
        __syncthreads();
    }

    const float rs = rsqrtf(1.f + 1e-5f);
#pragma unroll
    for (int nb = 0; nb < 8; nb++) {
        int c0 = nb * 8 + 2 * tg;
        int c1 = c0 + 1;
        float s0 = __ldg(&g[c0]) * rs, s1 = __ldg(&g[c1]) * rs;
        float bb0 = __ldg(&b[c0]), bb1 = __ldg(&b[c1]);
        float be0 = __ldg(&beta[c0]), be1 = __ldg(&beta[c1]);
        float f00 = lrelu((acc[nb][0] + bb0) * s0 + be0);
        float f01 = lrelu((acc[nb][1] + bb1) * s1 + be1);
        float f10 = lrelu((acc[nb][2] + bb0) * s0 + be0);
        float f11 = lrelu((acc[nb][3] + bb1) * s1 + be1);
        sX[(wr + gq) * XPITCH + c0]     = f2tf32(f00);
        sX[(wr + gq) * XPITCH + c1]     = f2tf32(f01);
        sX[(wr + gq + 8) * XPITCH + c0] = f2tf32(f10);
        sX[(wr + gq + 8) * XPITCH + c1] = f2tf32(f11);
        acc[nb][0] = 0.f; acc[nb][1] = 0.f; acc[nb][2] = 0.f; acc[nb][3] = 0.f;
    }
    {
        int wk = tid >> 2, ng = (tid & 3) * 16;
        const float4* src = reinterpret_cast<const float4*>(&Wg[(size_t)wk * 64 + ng]);
#pragma unroll
        for (int i = 0; i < 4; i++) {
            float4 v = __ldg(src + i);
            int n = ng + i * 4;
            sWt[(n + 0) * XPITCH + wk] = f2tf32(v.x);
            sWt[(n + 1) * XPITCH + wk] = f2tf32(v.y);
            sWt[(n + 2) * XPITCH + wk] = f2tf32(v.z);
            sWt[(n + 3) * XPITCH + wk] = f2tf32(v.w);
        }
    }
    __syncthreads();

#pragma unroll
    for (int ks = 0; ks < 8; ks++) {
        int k4 = ks * 8;
        uint32_t a0 = sX[(wr + gq) * XPITCH + k4 + tg];
        uint32_t a1 = sX[(wr + gq + 8) * XPITCH + k4 + tg];
        uint32_t a2 = sX[(wr + gq) * XPITCH + k4 + tg + 4];
        uint32_t a3 = sX[(wr + gq + 8) * XPITCH + k4 + tg + 4];
#pragma unroll
        for (int nb = 0; nb < 8; nb++) {
            uint32_t b0 = sWt[(nb * 8 + gq) * XPITCH + k4 + tg];
            uint32_t b1 = sWt[(nb * 8 + gq) * XPITCH + k4 + tg + 4];
            mma_tf32(acc[nb][0], acc[nb][1], acc[nb][2], acc[nb][3],
                     a0, a1, a2, a3, b0, b1);
        }
    }

    int rlo = r0 + wr + gq;
    int rhi = rlo + 8;
#pragma unroll
    for (int nb = 0; nb < 8; nb++) {
        int c0 = nb * 8 + 2 * tg;
        float bg0 = __ldg(&bg[c0]), bg1 = __ldg(&bg[c0 + 1]);
        if (rlo < NI) {
            float2 it = *reinterpret_cast<const float2*>(item_emb + (size_t)rlo * 64 + c0);
            float ox = it.x / (1.f + __expf(-(acc[nb][0] + bg0)));
            float oy = it.y / (1.f + __expf(-(acc[nb][1] + bg1)));
            *reinterpret_cast<__half2*>(outh + (size_t)rlo * 64 + c0) = __floats2half2_rn(ox, oy);
        }
        if (rhi < NI) {
            float2 it = *reinterpret_cast<const float2*>(item_emb + (size_t)rhi * 64 + c0);
            float ox = it.x / (1.f + __expf(-(acc[nb][2] + bg0)));
            float oy = it.y / (1.f + __expf(-(acc[nb][3] + bg1)));
            *reinterpret_cast<__half2*>(outh + (size_t)rhi * 64 + c0) = __floats2half2_rn(ox, oy);
        }
    }
}

// ---------------- attention fusion over a row range (writes out[1..3]) --------
__global__ __launch_bounds__(256, 2)
void att_kernel(const float* __restrict__ img_ui, const float* __restrict__ txt_ui,
                const float* __restrict__ W1, const float* __restrict__ b1,
                const float* __restrict__ w2, float* __restrict__ out,
                int r_begin, int r_end) {
    __shared__ float sei[4][64], set_[4][64];
    __shared__ float wsum[8][2];
    int d    = threadIdx.x & 63;
    int sub  = threadIdx.x >> 6;
    int warp = threadIdx.x >> 5;
    int lane = threadIdx.x & 31;

    float Wc[64];
#pragma unroll
    for (int k = 0; k < 64; k++) Wc[k] = __ldg(&W1[k * 64 + d]);
    float b1d = __ldg(&b1[d]);
    float w2d = __ldg(&w2[d]);

    int r0 = r_begin + blockIdx.x * 128;
#pragma unroll 1
    for (int i = 0; i < 32; i++) {
        int r = r0 + i * 4 + sub;
        bool valid = r < r_end;
        size_t base = (size_t)r * 64 + d;
        float ei = valid ? __ldg(&img_ui[base]) : 0.f;
        float et = valid ? __ldg(&txt_ui[base]) : 0.f;
        sei[sub][d]  = ei;
        set_[sub][d] = et;
        __syncthreads();

        float hi = b1d, ht = b1d;
#pragma unroll
        for (int k = 0; k < 64; k += 4) {
            float4 a = *reinterpret_cast<const float4*>(&sei[sub][k]);
            float4 b = *reinterpret_cast<const float4*>(&set_[sub][k]);
            hi += a.x * Wc[k] + a.y * Wc[k + 1] + a.z * Wc[k + 2] + a.w * Wc[k + 3];
            ht += b.x * Wc[k] + b.y * Wc[k + 1] + b.z * Wc[k + 2] + b.w * Wc[k + 3];
        }
        hi = lrelu(hi) * w2d;
        ht = lrelu(ht) * w2d;
#pragma unroll
        for (int o = 16; o; o >>= 1) {
            hi += __shfl_xor_sync(0xffffffffu, hi, o);
            ht += __shfl_xor_sync(0xffffffffu, ht, o);
        }
        if (lane == 0) { wsum[warp][0] = hi; wsum[warp][1] = ht; }
        __syncthreads();
        int wbase = sub * 2;
        float si = wsum[wbase][0] + wsum[wbase + 1][0];
        float st = wsum[wbase][1] + wsum[wbase + 1][1];
        float wimg = 1.f / (1.f + __expf(st - si));
        float common = wimg * ei + (1.f - wimg) * et;

        if (valid) {
            out[(size_t)1 * NN * DD + base] = ei - common;
            out[(size_t)2 * NN * DD + base] = et - common;
            out[(size_t)3 * NN * DD + base] = common;
        }
        __syncthreads();
    }
}

// ---------------- driver ------------------------------------------------------
static inline int g256(long long n) { return (int)((n + 255) / 256); }

extern "C" void kernel_launch(void* const* d_in, const int* in_sizes, int n_in,
                              void* d_out, int out_size) {
    const float* user_emb  = (const float*)d_in[0];
    const float* item_emb  = (const float*)d_in[1];
    const float* image_emb = (const float*)d_in[2];
    const float* text_emb  = (const float*)d_in[3];
    const float* W_img = (const float*)d_in[4];
    const float* b_img = (const float*)d_in[5];
    const float* bng_img = (const float*)d_in[6];
    const float* bnb_img = (const float*)d_in[7];
    const float* W_txt = (const float*)d_in[8];
    const float* b_txt = (const float*)d_in[9];
    const float* bng_txt = (const float*)d_in[10];
    const float* bnb_txt = (const float*)d_in[11];
    const float* W_gi = (const float*)d_in[12];
    const float* b_gi = (const float*)d_in[13];
    const float* W_gt = (const float*)d_in[14];
    const float* b_gt = (const float*)d_in[15];
    const float* W_c1 = (const float*)d_in[16];
    const float* b_c1 = (const float*)d_in[17];
    const float* w_c2 = (const float*)d_in[18];
    const float* ui_vals = (const float*)d_in[19];
    const float* R_vals  = (const float*)d_in[20];
    const float* ii_i_vals = (const float*)d_in[21];
    const float* ii_t_vals = (const float*)d_in[22];
    const int* ui_rows = (const int*)d_in[23];
    const int* ui_cols = (const int*)d_in[24];
    const int* R_rows  = (const int*)d_in[25];
    const int* R_cols  = (const int*)d_in[26];
    const int* ii_i_rows = (const int*)d_in[27];
    const int* ii_i_cols = (const int*)d_in[28];
    const int* ii_t_rows = (const int*)d_in[29];
    const int* ii_t_cols = (const int*)d_in[30];

    float* out = (float*)d_out;

    void* p;
    cudaGetSymbolAddress(&p, g_cat1);   float*  cat1   = (float*)p;
    cudaGetSymbolAddress(&p, g_cat2);   float*  cat2   = (float*)p;
    cudaGetSymbolAddress(&p, g_img_ui); float*  img_ui = (float*)p;
    cudaGetSymbolAddress(&p, g_txt_ui); float*  txt_ui = (float*)p;
    cudaGetSymbolAddress(&p, g_gi1);    float*  gi1    = (float*)p;
    cudaGetSymbolAddress(&p, g_gt1);    float*  gt1    = (float*)p;
    cudaGetSymbolAddress(&p, g_cat0h);  __half* cat0h  = (__half*)p;
    cudaGetSymbolAddress(&p, g_cat1h);  __half* cat1h  = (__half*)p;
    cudaGetSymbolAddress(&p, g_gi0h);   __half* gi0h   = (__half*)p;
    cudaGetSymbolAddress(&p, g_gi1h);   __half* gi1h   = (__half*)p;
    cudaGetSymbolAddress(&p, g_gt0h);   __half* gt0h   = (__half*)p;
    cudaGetSymbolAddress(&p, g_gt1h);   __half* gt1h   = (__half*)p;
    cudaGetSymbolAddress(&p, g_iih);    __half* iih    = (__half*)p;
    cudaGetSymbolAddress(&p, g_ith);    __half* ith    = (__half*)p;

    float* img_items = img_ui + (size_t)NU * DD;
    float* txt_items = txt_ui + (size_t)NU * DD;

    static cudaStream_t sA = nullptr, sB = nullptr, sC = nullptr;
    static cudaEvent_t eFork = nullptr, eA = nullptr, eB = nullptr, eC = nullptr;
    static cudaEvent_t eBh = nullptr, eCh = nullptr;
    if (!sA) {
        cudaStreamCreateWithFlags(&sA, cudaStreamNonBlocking);
        cudaStreamCreateWithFlags(&sB, cudaStreamNonBlocking);
        cudaStreamCreateWithFlags(&sC, cudaStreamNonBlocking);
        cudaEventCreateWithFlags(&eFork, cudaEventDisableTiming);
        cudaEventCreateWithFlags(&eA, cudaEventDisableTiming);
        cudaEventCreateWithFlags(&eB, cudaEventDisableTiming);
        cudaEventCreateWithFlags(&eC, cudaEventDisableTiming);
        cudaEventCreateWithFlags(&eBh, cudaEventDisableTiming);
        cudaEventCreateWithFlags(&eCh, cudaEventDisableTiming);
    }

    const int G_UI = NNZ_UI / 32;      // 8 thr/edge -> nnz*8/256
    const int G_II = NNZ_II / 32;
    const int G_R  = NNZ_R  / 32;
    const size_t NNB = (size_t)NN * DD * sizeof(float);
    const size_t NIB = (size_t)NI * DD * sizeof(float);
    const int NN4 = NN * 16, NI4 = NI * 16, NU4 = NU * 16;

    cudaEventRecord(eFork, 0);
    cudaStreamWaitEvent(sA, eFork, 0);
    cudaStreamWaitEvent(sB, eFork, 0);
    cudaStreamWaitEvent(sC, eFork, 0);

    // ---- chain A: ui GCN -> out[0] ----
    f2h_kernel<<<g256(NI4), 256, 0, sA>>>(item_emb, cat0h, NI4);
    f2h_kernel<<<g256(NU4), 256, 0, sA>>>(user_emb, cat0h + (size_t)NI * DD, NU4);
    cudaMemsetAsync(cat1, 0, NNB, sA);
    cudaMemsetAsync(cat2, 0, NNB, sA);
    spmm_h_kernel<<<G_UI, 256, 0, sA>>>(ui_rows, ui_cols, ui_vals, cat0h, cat1, NNZ_UI);
    f2h_kernel<<<g256(NN4), 256, 0, sA>>>(cat1, cat1h, NN4);
    spmm_h_kernel<<<G_UI, 256, 0, sA>>>(ui_rows, ui_cols, ui_vals, cat1h, cat2, NNZ_UI);
    mean3_cat_kernel<<<g256(NN4), 256, 0, sA>>>(item_emb, user_emb, cat1, cat2, out);
    cudaEventRecord(eA, sA);

    // ---- chain B: image branch through ii-hop2 + items fp16 ----
    cudaMemsetAsync(img_ui, 0, NNB, sB);
    cudaMemsetAsync(gi1, 0, NIB, sB);
    projgate_kernel<512><<<(NI + 127) / 128, 256, 0, sB>>>(image_emb, W_img, b_img, bng_img, bnb_img,
                                                           W_gi, b_gi, item_emb, gi0h);
    spmm_h_kernel<<<G_II, 256, 0, sB>>>(ii_i_rows, ii_i_cols, ii_i_vals, gi0h, gi1, NNZ_II);
    f2h_kernel<<<g256(NI4), 256, 0, sB>>>(gi1, gi1h, NI4);
    spmm_h_kernel<<<G_II, 256, 0, sB>>>(ii_i_rows, ii_i_cols, ii_i_vals, gi1h, img_items, NNZ_II);
    f2h_kernel<<<g256(NI4), 256, 0, sB>>>(img_items, iih, NI4);
    cudaEventRecord(eBh, sB);

    // ---- chain C: text branch through ii-hop2 + items fp16 ----
    cudaMemsetAsync(txt_ui, 0, NNB, sC);
    cudaMemsetAsync(gt1, 0, NIB, sC);
    projgate_kernel<384><<<(NI + 127) / 128, 256, 0, sC>>>(text_emb, W_txt, b_txt, bng_txt, bnb_txt,
                                                           W_gt, b_gt, item_emb, gt0h);
    spmm_h_kernel<<<G_II, 256, 0, sC>>>(ii_t_rows, ii_t_cols, ii_t_vals, gt0h, gt1, NNZ_II);
    f2h_kernel<<<g256(NI4), 256, 0, sC>>>(gt1, gt1h, NI4);
    spmm_h_kernel<<<G_II, 256, 0, sC>>>(ii_t_rows, ii_t_cols, ii_t_vals, gt1h, txt_items, NNZ_II);
    f2h_kernel<<<g256(NI4), 256, 0, sC>>>(txt_items, ith, NI4);
    cudaEventRecord(eCh, sC);

    // ---- B: dualR (user rows) + att over user rows ----
    cudaStreamWaitEvent(sB, eCh, 0);
    spmm_dualR_h_kernel<<<G_R, 256, 0, sB>>>(R_rows, R_cols, R_vals, iih, ith,
                                             img_ui, txt_ui, NNZ_R);
    att_kernel<<<(NU + 127) / 128, 256, 0, sB>>>(img_ui, txt_ui, W_c1, b_c1, w_c2, out, 0, NU);
    cudaEventRecord(eB, sB);

    // ---- C: att over item rows, concurrent with dualR ----
    cudaStreamWaitEvent(sC, eBh, 0);
    att_kernel<<<(NI + 127) / 128, 256, 0, sC>>>(img_ui, txt_ui, W_c1, b_c1, w_c2, out, NU, NN);
    cudaEventRecord(eC, sC);

    // ---- join ----
    cudaStreamWaitEvent(0, eA, 0);
    cudaStreamWaitEvent(0, eB, 0);
    cudaStreamWaitEvent(0, eC, 0);
}

// round 10
// speedup vs baseline: 1.4083x; 1.4083x over previous
#include <cuda_runtime.h>
#include <math.h>
#include <stdint.h>

#define NU 50000
#define NI 30000
#define NN 80000
#define DD 64

#define NNZ_UI 1000000
#define NNZ_R  800000
#define NNZ_II 300000

// ---------------- scratch (static device globals) -----------------------------
__device__ float g_cat1[NN * DD];
__device__ float g_img_ui[NN * DD];
__device__ float g_txt_ui[NN * DD];
__device__ float g_gi0[NI * DD];
__device__ float g_gi1[NI * DD];
__device__ float g_gt0[NI * DD];
__device__ float g_gt1[NI * DD];

// CSR sort scratch: cnt doubles as scatter cursor after scan copies into it.
__device__ int   g_ui_cnt[NN + 1];
__device__ int   g_ui_off[NN + 1];
__device__ int   g_ui_scol[NNZ_UI];
__device__ float g_ui_sval[NNZ_UI];
__device__ int   g_R_cnt[NU + 1];
__device__ int   g_R_off[NU + 1];
__device__ int   g_R_scol[NNZ_R];
__device__ float g_R_sval[NNZ_R];
__device__ int   g_i_cnt[NI + 1];
__device__ int   g_i_off[NI + 1];
__device__ int   g_i_scol[NNZ_II];
__device__ float g_i_sval[NNZ_II];
__device__ int   g_t_cnt[NI + 1];
__device__ int   g_t_off[NI + 1];
__device__ int   g_t_scol[NNZ_II];
__device__ float g_t_sval[NNZ_II];

__device__ __forceinline__ float lrelu(float x) { return x >= 0.f ? x : 0.01f * x; }

__device__ __forceinline__ uint32_t f2tf32(float f) {
    uint32_t r;
    asm("cvt.rna.tf32.f32 %0, %1;" : "=r"(r) : "f"(f));
    return r;
}

__device__ __forceinline__ void mma_tf32(float& c0, float& c1, float& c2, float& c3,
                                         uint32_t a0, uint32_t a1, uint32_t a2, uint32_t a3,
                                         uint32_t b0, uint32_t b1) {
    asm("mma.sync.aligned.m16n8k8.row.col.f32.tf32.tf32.f32 "
        "{%0,%1,%2,%3}, {%4,%5,%6,%7}, {%8,%9}, {%0,%1,%2,%3};"
        : "+f"(c0), "+f"(c1), "+f"(c2), "+f"(c3)
        : "r"(a0), "r"(a1), "r"(a2), "r"(a3), "r"(b0), "r"(b1));
}

// ================= counting sort (row-CSR) ======================================
__global__ void hist_kernel(const int* __restrict__ rows, int* __restrict__ cnt, int nnz) {
    int i = blockIdx.x * blockDim.x + threadIdx.x;
    if (i < nnz) atomicAdd(&cnt[__ldg(&rows[i])], 1);
}

// single-block exclusive scan: off[0..n-1] = exclusive prefix of cnt, off[n] = total
__global__ void scan_kernel(const int* __restrict__ cnt, int* __restrict__ off, int n) {
    __shared__ int wsum[32];
    __shared__ int carry;
    int tid = threadIdx.x, lane = tid & 31, wid = tid >> 5;
    if (tid == 0) carry = 0;
    __syncthreads();
    for (int base = 0; base < n; base += 1024) {
        int idx = base + tid;
        int v = (idx < n) ? __ldg(&cnt[idx]) : 0;
        int incl = v;
#pragma unroll
        for (int o = 1; o < 32; o <<= 1) {
            int t = __shfl_up_sync(0xffffffffu, incl, o);
            if (lane >= o) incl += t;
        }
        if (lane == 31) wsum[wid] = incl;
        __syncthreads();
        if (wid == 0) {
            int s = wsum[lane];
#pragma unroll
            for (int o = 1; o < 32; o <<= 1) {
                int t = __shfl_up_sync(0xffffffffu, s, o);
                if (lane >= o) s += t;
            }
            wsum[lane] = s;
        }
        __syncthreads();
        int wprev = (wid == 0) ? 0 : wsum[wid - 1];
        int excl = carry + wprev + incl - v;
        if (idx < n) off[idx] = excl;
        int total = wsum[31];
        __syncthreads();
        if (tid == 0) carry += total;
        __syncthreads();
    }
    if (threadIdx.x == 0) off[n] = carry;
}

__global__ void copy_int_kernel(const int* __restrict__ src, int* __restrict__ dst, int n) {
    int i = blockIdx.x * blockDim.x + threadIdx.x;
    if (i < n) dst[i] = __ldg(&src[i]);
}

__global__ void scatter_kernel(const int* __restrict__ rows, const int* __restrict__ cols,
                               const float* __restrict__ vals, int* __restrict__ pos,
                               int* __restrict__ scol, float* __restrict__ sval, int nnz) {
    int i = blockIdx.x * blockDim.x + threadIdx.x;
    if (i >= nnz) return;
    int p = atomicAdd(&pos[__ldg(&rows[i])], 1);
    scol[p] = __ldg(&cols[i]);
    sval[p] = __ldg(&vals[i]);
}

// ================= CSR spMM (warp per row, float2 per lane) ====================
__global__ void csr_plain_kernel(const int* __restrict__ off, const int* __restrict__ scol,
                                 const float* __restrict__ sval, const float* __restrict__ x,
                                 float* __restrict__ out, int nrows) {
    int w = (blockIdx.x * blockDim.x + threadIdx.x) >> 5;
    int lane = threadIdx.x & 31;
    if (w >= nrows) return;
    int s = __ldg(&off[w]), e = __ldg(&off[w + 1]);
    float2 acc = make_float2(0.f, 0.f);
    int i = s;
    for (; i + 1 < e; i += 2) {
        int c0 = __ldg(&scol[i]), c1 = __ldg(&scol[i + 1]);
        float v0 = __ldg(&sval[i]), v1 = __ldg(&sval[i + 1]);
        float2 x0 = __ldg(reinterpret_cast<const float2*>(x) + (size_t)c0 * 32 + lane);
        float2 x1 = __ldg(reinterpret_cast<const float2*>(x) + (size_t)c1 * 32 + lane);
        acc.x += v0 * x0.x + v1 * x1.x;
        acc.y += v0 * x0.y + v1 * x1.y;
    }
    if (i < e) {
        int c = __ldg(&scol[i]);
        float v = __ldg(&sval[i]);
        float2 xv = __ldg(reinterpret_cast<const float2*>(x) + (size_t)c * 32 + lane);
        acc.x += v * xv.x;
        acc.y += v * xv.y;
    }
    reinterpret_cast<float2*>(out)[(size_t)w * 32 + lane] = acc;
}

// hop1 over virtual concat [item_emb ; user_emb]
__global__ void csr_cat_kernel(const int* __restrict__ off, const int* __restrict__ scol,
                               const float* __restrict__ sval,
                               const float* __restrict__ item_emb, const float* __restrict__ user_emb,
                               float* __restrict__ out, int nrows) {
    int w = (blockIdx.x * blockDim.x + threadIdx.x) >> 5;
    int lane = threadIdx.x & 31;
    if (w >= nrows) return;
    int s = __ldg(&off[w]), e = __ldg(&off[w + 1]);
    float2 acc = make_float2(0.f, 0.f);
    int i = s;
    for (; i + 1 < e; i += 2) {
        int c0 = __ldg(&scol[i]), c1 = __ldg(&scol[i + 1]);
        float v0 = __ldg(&sval[i]), v1 = __ldg(&sval[i + 1]);
        const float2* p0 = (c0 < NI)
            ? reinterpret_cast<const float2*>(item_emb) + (size_t)c0 * 32
            : reinterpret_cast<const float2*>(user_emb) + (size_t)(c0 - NI) * 32;
        const float2* p1 = (c1 < NI)
            ? reinterpret_cast<const float2*>(item_emb) + (size_t)c1 * 32
            : reinterpret_cast<const float2*>(user_emb) + (size_t)(c1 - NI) * 32;
        float2 x0 = __ldg(p0 + lane), x1 = __ldg(p1 + lane);
        acc.x += v0 * x0.x + v1 * x1.x;
        acc.y += v0 * x0.y + v1 * x1.y;
    }
    if (i < e) {
        int c = __ldg(&scol[i]);
        float v = __ldg(&sval[i]);
        const float2* p = (c < NI)
            ? reinterpret_cast<const float2*>(item_emb) + (size_t)c * 32
            : reinterpret_cast<const float2*>(user_emb) + (size_t)(c - NI) * 32;
        float2 xv = __ldg(p + lane);
        acc.x += v * xv.x;
        acc.y += v * xv.y;
    }
    reinterpret_cast<float2*>(out)[(size_t)w * 32 + lane] = acc;
}

// hop2 + fused mean: out0[w] = (cat0v[w] + cat1[w] + A@cat1[w]) / 3
__global__ void csr_mean_kernel(const int* __restrict__ off, const int* __restrict__ scol,
                                const float* __restrict__ sval, const float* __restrict__ cat1,
                                const float* __restrict__ item_emb, const float* __restrict__ user_emb,
                                float* __restrict__ out, int nrows) {
    int w = (blockIdx.x * blockDim.x + threadIdx.x) >> 5;
    int lane = threadIdx.x & 31;
    if (w >= nrows) return;
    int s = __ldg(&off[w]), e = __ldg(&off[w + 1]);
    float2 acc = make_float2(0.f, 0.f);
    int i = s;
    for (; i + 1 < e; i += 2) {
        int c0 = __ldg(&scol[i]), c1 = __ldg(&scol[i + 1]);
        float v0 = __ldg(&sval[i]), v1 = __ldg(&sval[i + 1]);
        float2 x0 = __ldg(reinterpret_cast<const float2*>(cat1) + (size_t)c0 * 32 + lane);
        float2 x1 = __ldg(reinterpret_cast<const float2*>(cat1) + (size_t)c1 * 32 + lane);
        acc.x += v0 * x0.x + v1 * x1.x;
        acc.y += v0 * x0.y + v1 * x1.y;
    }
    if (i < e) {
        int c = __ldg(&scol[i]);
        float v = __ldg(&sval[i]);
        float2 xv = __ldg(reinterpret_cast<const float2*>(cat1) + (size_t)c * 32 + lane);
        acc.x += v * xv.x;
        acc.y += v * xv.y;
    }
    const float2* a0p = (w < NI)
        ? reinterpret_cast<const float2*>(item_emb) + (size_t)w * 32
        : reinterpret_cast<const float2*>(user_emb) + (size_t)(w - NI) * 32;
    float2 a0 = __ldg(a0p + lane);
    float2 b0 = __ldg(reinterpret_cast<const float2*>(cat1) + (size_t)w * 32 + lane);
    const float third = 1.f / 3.f;
    float2 o;
    o.x = (a0.x + b0.x + acc.x) * third;
    o.y = (a0.y + b0.y + acc.y) * third;
    reinterpret_cast<float2*>(out)[(size_t)w * 32 + lane] = o;
}

// R: dual gather (img/txt items), writes user rows of both outputs
__global__ void csr_dual_kernel(const int* __restrict__ off, const int* __restrict__ scol,
                                const float* __restrict__ sval,
                                const float* __restrict__ xi, const float* __restrict__ xt,
                                float* __restrict__ oi, float* __restrict__ ot, int nrows) {
    int w = (blockIdx.x * blockDim.x + threadIdx.x) >> 5;
    int lane = threadIdx.x & 31;
    if (w >= nrows) return;
    int s = __ldg(&off[w]), e = __ldg(&off[w + 1]);
    float2 ai = make_float2(0.f, 0.f), at = make_float2(0.f, 0.f);
    for (int i = s; i < e; i++) {
        int c = __ldg(&scol[i]);
        float v = __ldg(&sval[i]);
        float2 x0 = __ldg(reinterpret_cast<const float2*>(xi) + (size_t)c * 32 + lane);
        float2 x1 = __ldg(reinterpret_cast<const float2*>(xt) + (size_t)c * 32 + lane);
        ai.x += v * x0.x; ai.y += v * x0.y;
        at.x += v * x1.x; at.y += v * x1.y;
    }
    reinterpret_cast<float2*>(oi)[(size_t)w * 32 + lane] = ai;
    reinterpret_cast<float2*>(ot)[(size_t)w * 32 + lane] = at;
}

// ================= tf32 projection + BN + lrelu + gate =========================
#define XPITCH 68
template <int F>
__global__ __launch_bounds__(256)
void projgate_kernel(const float* __restrict__ x, const float* __restrict__ W,
                     const float* __restrict__ b, const float* __restrict__ g,
                     const float* __restrict__ beta,
                     const float* __restrict__ Wg, const float* __restrict__ bg,
                     const float* __restrict__ item_emb,
                     float* __restrict__ out) {
    __shared__ uint32_t sX[128 * XPITCH];
    __shared__ uint32_t sWt[64 * XPITCH];

    const int tid  = threadIdx.x;
    const int warp = tid >> 5;
    const int lane = tid & 31;
    const int gq   = lane >> 2;
    const int tg   = lane & 3;
    const int wr   = warp * 16;
    const int r0   = blockIdx.x * 128;

    float acc[8][4];
#pragma unroll
    for (int nb = 0; nb < 8; nb++)
#pragma unroll
        for (int i = 0; i < 4; i++) acc[nb][i] = 0.f;

    for (int kc = 0; kc < F; kc += 64) {
        {
            int lr = tid >> 1, half = tid & 1;
            int gr = r0 + lr;
            uint32_t* dst = &sX[lr * XPITCH + half * 32];
            if (gr < NI) {
                const float4* src = reinterpret_cast<const float4*>(x + (size_t)gr * F + kc) + half * 8;
#pragma unroll
                for (int i = 0; i < 8; i++) {
                    float4 v = __ldg(src + i);
                    dst[i * 4 + 0] = f2tf32(v.x);
                    dst[i * 4 + 1] = f2tf32(v.y);
                    dst[i * 4 + 2] = f2tf32(v.z);
                    dst[i * 4 + 3] = f2tf32(v.w);
                }
            } else {
#pragma unroll
                for (int i = 0; i < 32; i++) dst[i] = 0u;
            }
        }
        {
            int wk = tid >> 2, ng = (tid & 3) * 16;
            const float4* src = reinterpret_cast<const float4*>(&W[(size_t)(kc + wk) * 64 + ng]);
#pragma unroll
            for (int i = 0; i < 4; i++) {
                float4 v = __ldg(src + i);
                int n = ng + i * 4;
                sWt[(n + 0) * XPITCH + wk] = f2tf32(v.x);
                sWt[(n + 1) * XPITCH + wk] = f2tf32(v.y);
                sWt[(n + 2) * XPITCH + wk] = f2tf32(v.z);
                sWt[(n + 3) * XPITCH + wk] = f2tf32(v.w);
            }
        }
        __syncthreads();

#pragma unroll
        for (int ks = 0; ks < 8; ks++) {
            int k4 = ks * 8;
            uint32_t a0 = sX[(wr + gq) * XPITCH + k4 + tg];
            uint32_t a1 = sX[(wr + gq + 8) * XPITCH + k4 + tg];
            uint32_t a2 = sX[(wr + gq) * XPITCH + k4 + tg + 4];
            uint32_t a3 = sX[(wr + gq + 8) * XPITCH + k4 + tg + 4];
#pragma unroll
            for (int nb = 0; nb < 8; nb++) {
                uint32_t b0 = sWt[(nb * 8 + gq) * XPITCH + k4 + tg];
                uint32_t b1 = sWt[(nb * 8 + gq) * XPITCH + k4 + tg + 4];
                mma_tf32(acc[nb][0], acc[nb][1], acc[nb][2], acc[nb][3],
                         a0, a1, a2, a3, b0, b1);
            }
        }
        __syncthreads();
    }

    const float rs = rsqrtf(1.f + 1e-5f);
#pragma unroll
    for (int nb = 0; nb < 8; nb++) {
        int c0 = nb * 8 + 2 * tg;
        int c1 = c0 + 1;
        float s0 = __ldg(&g[c0]) * rs, s1 = __ldg(&g[c1]) * rs;
        float bb0 = __ldg(&b[c0]), bb1 = __ldg(&b[c1]);
        float be0 = __ldg(&beta[c0]), be1 = __ldg(&beta[c1]);
        float f00 = lrelu((acc[nb][0] + bb0) * s0 + be0);
        float f01 = lrelu((acc[nb][1] + bb1) * s1 + be1);
        float f10 = lrelu((acc[nb][2] + bb0) * s0 + be0);
        float f11 = lrelu((acc[nb][3] + bb1) * s1 + be1);
        sX[(wr + gq) * XPITCH + c0]     = f2tf32(f00);
        sX[(wr + gq) * XPITCH + c1]     = f2tf32(f01);
        sX[(wr + gq + 8) * XPITCH + c0] = f2tf32(f10);
        sX[(wr + gq + 8) * XPITCH + c1] = f2tf32(f11);
        acc[nb][0] = 0.f; acc[nb][1] = 0.f; acc[nb][2] = 0.f; acc[nb][3] = 0.f;
    }
    {
        int wk = tid >> 2, ng = (tid & 3) * 16;
        const float4* src = reinterpret_cast<const float4*>(&Wg[(size_t)wk * 64 + ng]);
#pragma unroll
        for (int i = 0; i < 4; i++) {
            float4 v = __ldg(src + i);
            int n = ng + i * 4;
            sWt[(n + 0) * XPITCH + wk] = f2tf32(v.x);
            sWt[(n + 1) * XPITCH + wk] = f2tf32(v.y);
            sWt[(n + 2) * XPITCH + wk] = f2tf32(v.z);
            sWt[(n + 3) * XPITCH + wk] = f2tf32(v.w);
        }
    }
    __syncthreads();

#pragma unroll
    for (int ks = 0; ks < 8; ks++) {
        int k4 = ks * 8;
        uint32_t a0 = sX[(wr + gq) * XPITCH + k4 + tg];
        uint32_t a1 = sX[(wr + gq + 8) * XPITCH + k4 + tg];
        uint32_t a2 = sX[(wr + gq) * XPITCH + k4 + tg + 4];
        uint32_t a3 = sX[(wr + gq + 8) * XPITCH + k4 + tg + 4];
#pragma unroll
        for (int nb = 0; nb < 8; nb++) {
            uint32_t b0 = sWt[(nb * 8 + gq) * XPITCH + k4 + tg];
            uint32_t b1 = sWt[(nb * 8 + gq) * XPITCH + k4 + tg + 4];
            mma_tf32(acc[nb][0], acc[nb][1], acc[nb][2], acc[nb][3],
                     a0, a1, a2, a3, b0, b1);
        }
    }

    int rlo = r0 + wr + gq;
    int rhi = rlo + 8;
#pragma unroll
    for (int nb = 0; nb < 8; nb++) {
        int c0 = nb * 8 + 2 * tg;
        float bg0 = __ldg(&bg[c0]), bg1 = __ldg(&bg[c0 + 1]);
        if (rlo < NI) {
            float2 it = *reinterpret_cast<const float2*>(item_emb + (size_t)rlo * 64 + c0);
            float2 o;
            o.x = it.x / (1.f + __expf(-(acc[nb][0] + bg0)));
            o.y = it.y / (1.f + __expf(-(acc[nb][1] + bg1)));
            *reinterpret_cast<float2*>(out + (size_t)rlo * 64 + c0) = o;
        }
        if (rhi < NI) {
            float2 it = *reinterpret_cast<const float2*>(item_emb + (size_t)rhi * 64 + c0);
            float2 o;
            o.x = it.x / (1.f + __expf(-(acc[nb][2] + bg0)));
            o.y = it.y / (1.f + __expf(-(acc[nb][3] + bg1)));
            *reinterpret_cast<float2*>(out + (size_t)rhi * 64 + c0) = o;
        }
    }
}

// ---------------- attention fusion over a row range (writes out[1..3]) --------
__global__ __launch_bounds__(256, 2)
void att_kernel(const float* __restrict__ img_ui, const float* __restrict__ txt_ui,
                const float* __restrict__ W1, const float* __restrict__ b1,
                const float* __restrict__ w2, float* __restrict__ out,
                int r_begin, int r_end) {
    __shared__ float sei[4][64], set_[4][64];
    __shared__ float wsum[8][2];
    int d    = threadIdx.x & 63;
    int sub  = threadIdx.x >> 6;
    int warp = threadIdx.x >> 5;
    int lane = threadIdx.x & 31;

    float Wc[64];
#pragma unroll
    for (int k = 0; k < 64; k++) Wc[k] = __ldg(&W1[k * 64 + d]);
    float b1d = __ldg(&b1[d]);
    float w2d = __ldg(&w2[d]);

    int r0 = r_begin + blockIdx.x * 128;
#pragma unroll 1
    for (int i = 0; i < 32; i++) {
        int r = r0 + i * 4 + sub;
        bool valid = r < r_end;
        size_t base = (size_t)r * 64 + d;
        float ei = valid ? __ldg(&img_ui[base]) : 0.f;
        float et = valid ? __ldg(&txt_ui[base]) : 0.f;
        sei[sub][d]  = ei;
        set_[sub][d] = et;
        __syncthreads();

        float hi = b1d, ht = b1d;
#pragma unroll
        for (int k = 0; k < 64; k += 4) {
            float4 a = *reinterpret_cast<const float4*>(&sei[sub][k]);
            float4 b = *reinterpret_cast<const float4*>(&set_[sub][k]);
            hi += a.x * Wc[k] + a.y * Wc[k + 1] + a.z * Wc[k + 2] + a.w * Wc[k + 3];
            ht += b.x * Wc[k] + b.y * Wc[k + 1] + b.z * Wc[k + 2] + b.w * Wc[k + 3];
        }
        hi = lrelu(hi) * w2d;
        ht = lrelu(ht) * w2d;
#pragma unroll
        for (int o = 16; o; o >>= 1) {
            hi += __shfl_xor_sync(0xffffffffu, hi, o);
            ht += __shfl_xor_sync(0xffffffffu, ht, o);
        }
        if (lane == 0) { wsum[warp][0] = hi; wsum[warp][1] = ht; }
        __syncthreads();
        int wbase = sub * 2;
        float si = wsum[wbase][0] + wsum[wbase + 1][0];
        float st = wsum[wbase][1] + wsum[wbase + 1][1];
        float wimg = 1.f / (1.f + __expf(st - si));
        float common = wimg * ei + (1.f - wimg) * et;

        if (valid) {
            out[(size_t)1 * NN * DD + base] = ei - common;
            out[(size_t)2 * NN * DD + base] = et - common;
            out[(size_t)3 * NN * DD + base] = common;
        }
        __syncthreads();
    }
}

// ---------------- driver ------------------------------------------------------
static inline int g256(long long n) { return (int)((n + 255) / 256); }

extern "C" void kernel_launch(void* const* d_in, const int* in_sizes, int n_in,
                              void* d_out, int out_size) {
    const float* user_emb  = (const float*)d_in[0];
    const float* item_emb  = (const float*)d_in[1];
    const float* image_emb = (const float*)d_in[2];
    const float* text_emb  = (const float*)d_in[3];
    const float* W_img = (const float*)d_in[4];
    const float* b_img = (const float*)d_in[5];
    const float* bng_img = (const float*)d_in[6];
    const float* bnb_img = (const float*)d_in[7];
    const float* W_txt = (const float*)d_in[8];
    const float* b_txt = (const float*)d_in[9];
    const float* bng_txt = (const float*)d_in[10];
    const float* bnb_txt = (const float*)d_in[11];
    const float* W_gi = (const float*)d_in[12];
    const float* b_gi = (const float*)d_in[13];
    const float* W_gt = (const float*)d_in[14];
    const float* b_gt = (const float*)d_in[15];
    const float* W_c1 = (const float*)d_in[16];
    const float* b_c1 = (const float*)d_in[17];
    const float* w_c2 = (const float*)d_in[18];
    const float* ui_vals = (const float*)d_in[19];
    const float* R_vals  = (const float*)d_in[20];
    const float* ii_i_vals = (const float*)d_in[21];
    const float* ii_t_vals = (const float*)d_in[22];
    const int* ui_rows = (const int*)d_in[23];
    const int* ui_cols = (const int*)d_in[24];
    const int* R_rows  = (const int*)d_in[25];
    const int* R_cols  = (const int*)d_in[26];
    const int* ii_i_rows = (const int*)d_in[27];
    const int* ii_i_cols = (const int*)d_in[28];
    const int* ii_t_rows = (const int*)d_in[29];
    const int* ii_t_cols = (const int*)d_in[30];

    float* out = (float*)d_out;

    void* p;
    cudaGetSymbolAddress(&p, g_cat1);    float* cat1   = (float*)p;
    cudaGetSymbolAddress(&p, g_img_ui);  float* img_ui = (float*)p;
    cudaGetSymbolAddress(&p, g_txt_ui);  float* txt_ui = (float*)p;
    cudaGetSymbolAddress(&p, g_gi0);     float* gi0    = (float*)p;
    cudaGetSymbolAddress(&p, g_gi1);     float* gi1    = (float*)p;
    cudaGetSymbolAddress(&p, g_gt0);     float* gt0    = (float*)p;
    cudaGetSymbolAddress(&p, g_gt1);     float* gt1    = (float*)p;
    cudaGetSymbolAddress(&p, g_ui_cnt);  int*   ui_cnt = (int*)p;
    cudaGetSymbolAddress(&p, g_ui_off);  int*   ui_off = (int*)p;
    cudaGetSymbolAddress(&p, g_ui_scol); int*   ui_scol = (int*)p;
    cudaGetSymbolAddress(&p, g_ui_sval); float* ui_sval = (float*)p;
    cudaGetSymbolAddress(&p, g_R_cnt);   int*   R_cnt  = (int*)p;
    cudaGetSymbolAddress(&p, g_R_off);   int*   R_off  = (int*)p;
    cudaGetSymbolAddress(&p, g_R_scol);  int*   R_scol = (int*)p;
    cudaGetSymbolAddress(&p, g_R_sval);  float* R_sval = (float*)p;
    cudaGetSymbolAddress(&p, g_i_cnt);   int*   i_cnt  = (int*)p;
    cudaGetSymbolAddress(&p, g_i_off);   int*   i_off  = (int*)p;
    cudaGetSymbolAddress(&p, g_i_scol);  int*   i_scol = (int*)p;
    cudaGetSymbolAddress(&p, g_i_sval);  float* i_sval = (float*)p;
    cudaGetSymbolAddress(&p, g_t_cnt);   int*   t_cnt  = (int*)p;
    cudaGetSymbolAddress(&p, g_t_off);   int*   t_off  = (int*)p;
    cudaGetSymbolAddress(&p, g_t_scol);  int*   t_scol = (int*)p;
    cudaGetSymbolAddress(&p, g_t_sval);  float* t_sval = (float*)p;

    float* img_items = img_ui + (size_t)NU * DD;
    float* txt_items = txt_ui + (size_t)NU * DD;

    static cudaStream_t sA = nullptr, sB = nullptr, sC = nullptr;
    static cudaEvent_t eFork = nullptr, eA = nullptr, eB = nullptr, eC = nullptr;
    static cudaEvent_t eBh = nullptr, eCh = nullptr, eR = nullptr;
    if (!sA) {
        cudaStreamCreateWithFlags(&sA, cudaStreamNonBlocking);
        cudaStreamCreateWithFlags(&sB, cudaStreamNonBlocking);
        cudaStreamCreateWithFlags(&sC, cudaStreamNonBlocking);
        cudaEventCreateWithFlags(&eFork, cudaEventDisableTiming);
        cudaEventCreateWithFlags(&eA, cudaEventDisableTiming);
        cudaEventCreateWithFlags(&eB, cudaEventDisableTiming);
        cudaEventCreateWithFlags(&eC, cudaEventDisableTiming);
        cudaEventCreateWithFlags(&eBh, cudaEventDisableTiming);
        cudaEventCreateWithFlags(&eCh, cudaEventDisableTiming);
        cudaEventCreateWithFlags(&eR, cudaEventDisableTiming);
    }

    cudaEventRecord(eFork, 0);
    cudaStreamWaitEvent(sA, eFork, 0);
    cudaStreamWaitEvent(sB, eFork, 0);
    cudaStreamWaitEvent(sC, eFork, 0);

    // ---- chain A: sort R (needed late by dualR), sort ui, ui GCN -> out[0] ----
    cudaMemsetAsync(R_cnt, 0, (NU + 1) * sizeof(int), sA);
    hist_kernel<<<g256(NNZ_R), 256, 0, sA>>>(R_rows, R_cnt, NNZ_R);
    scan_kernel<<<1, 1024, 0, sA>>>(R_cnt, R_off, NU);
    copy_int_kernel<<<g256(NU), 256, 0, sA>>>(R_off, R_cnt, NU);
    scatter_kernel<<<g256(NNZ_R), 256, 0, sA>>>(R_rows, R_cols, R_vals, R_cnt, R_scol, R_sval, NNZ_R);
    cudaEventRecord(eR, sA);

    cudaMemsetAsync(ui_cnt, 0, (NN + 1) * sizeof(int), sA);
    hist_kernel<<<g256(NNZ_UI), 256, 0, sA>>>(ui_rows, ui_cnt, NNZ_UI);
    scan_kernel<<<1, 1024, 0, sA>>>(ui_cnt, ui_off, NN);
    copy_int_kernel<<<g256(NN), 256, 0, sA>>>(ui_off, ui_cnt, NN);
    scatter_kernel<<<g256(NNZ_UI), 256, 0, sA>>>(ui_rows, ui_cols, ui_vals, ui_cnt, ui_scol, ui_sval, NNZ_UI);
    csr_cat_kernel<<<g256((long long)NN * 32), 256, 0, sA>>>(ui_off, ui_scol, ui_sval,
                                                             item_emb, user_emb, cat1, NN);
    csr_mean_kernel<<<g256((long long)NN * 32), 256, 0, sA>>>(ui_off, ui_scol, ui_sval, cat1,
                                                              item_emb, user_emb, out, NN);
    cudaEventRecord(eA, sA);

    // ---- chain B: image branch ----
    projgate_kernel<512><<<(NI + 127) / 128, 256, 0, sB>>>(image_emb, W_img, b_img, bng_img, bnb_img,
                                                           W_gi, b_gi, item_emb, gi0);
    cudaMemsetAsync(i_cnt, 0, (NI + 1) * sizeof(int), sB);
    hist_kernel<<<g256(NNZ_II), 256, 0, sB>>>(ii_i_rows, i_cnt, NNZ_II);
    scan_kernel<<<1, 1024, 0, sB>>>(i_cnt, i_off, NI);
    copy_int_kernel<<<g256(NI), 256, 0, sB>>>(i_off, i_cnt, NI);
    scatter_kernel<<<g256(NNZ_II), 256, 0, sB>>>(ii_i_rows, ii_i_cols, ii_i_vals, i_cnt, i_scol, i_sval, NNZ_II);
    csr_plain_kernel<<<g256((long long)NI * 32), 256, 0, sB>>>(i_off, i_scol, i_sval, gi0, gi1, NI);
    csr_plain_kernel<<<g256((long long)NI * 32), 256, 0, sB>>>(i_off, i_scol, i_sval, gi1, img_items, NI);
    cudaEventRecord(eBh, sB);

    // ---- chain C: text branch ----
    projgate_kernel<384><<<(NI + 127) / 128, 256, 0, sC>>>(text_emb, W_txt, b_txt, bng_txt, bnb_txt,
                                                           W_gt, b_gt, item_emb, gt0);
    cudaMemsetAsync(t_cnt, 0, (NI + 1) * sizeof(int), sC);
    hist_kernel<<<g256(NNZ_II), 256, 0, sC>>>(ii_t_rows, t_cnt, NNZ_II);
    scan_kernel<<<1, 1024, 0, sC>>>(t_cnt, t_off, NI);
    copy_int_kernel<<<g256(NI), 256, 0, sC>>>(t_off, t_cnt, NI);
    scatter_kernel<<<g256(NNZ_II), 256, 0, sC>>>(ii_t_rows, ii_t_cols, ii_t_vals, t_cnt, t_scol, t_sval, NNZ_II);
    csr_plain_kernel<<<g256((long long)NI * 32), 256, 0, sC>>>(t_off, t_scol, t_sval, gt0, gt1, NI);
    csr_plain_kernel<<<g256((long long)NI * 32), 256, 0, sC>>>(t_off, t_scol, t_sval, gt1, txt_items, NI);
    cudaEventRecord(eCh, sC);

    // ---- B: dualR (user rows of img_ui/txt_ui) + att over user rows ----
    cudaStreamWaitEvent(sB, eCh, 0);
    cudaStreamWaitEvent(sB, eR, 0);
    csr_dual_kernel<<<g256((long long)NU * 32), 256, 0, sB>>>(R_off, R_scol, R_sval,
                                                              img_items, txt_items,
                                                              img_ui, txt_ui, NU);
    att_kernel<<<(NU + 127) / 128, 256, 0, sB>>>(img_ui, txt_ui, W_c1, b_c1, w_c2, out, 0, NU);
    cudaEventRecord(eB, sB);

    // ---- C: att over item rows, concurrent with dualR ----
    cudaStreamWaitEvent(sC, eBh, 0);
    att_kernel<<<(NI + 127) / 128, 256, 0, sC>>>(img_ui, txt_ui, W_c1, b_c1, w_c2, out, NU, NN);
    cudaEventRecord(eC, sC);

    // ---- join ----
    cudaStreamWaitEvent(0, eA, 0);
    cudaStreamWaitEvent(0, eB, 0);
    cudaStreamWaitEvent(0, eC, 0);
}